// round 9
// baseline (speedup 1.0000x reference)
#include <cuda_runtime.h>
#include <cuda_bf16.h>

#define S 512
#define BB 512
#define T 64

__device__ float g_den[BB];
__device__ float g_num[BB];
__device__ unsigned g_tick = 0;   // wraps via atomicInc; never reset

typedef unsigned long long u64;

__device__ __forceinline__ u64 ffma2(u64 a, u64 b, u64 c) {
    u64 d; asm("fma.rn.f32x2 %0, %1, %2, %3;" : "=l"(d) : "l"(a), "l"(b), "l"(c)); return d;
}
__device__ __forceinline__ u64 fadd2(u64 a, u64 b) {
    u64 d; asm("add.rn.f32x2 %0, %1, %2;" : "=l"(d) : "l"(a), "l"(b)); return d;
}
__device__ __forceinline__ u64 pack2(float x, float y) {
    u64 d; asm("mov.b64 %0, {%1, %2};" : "=l"(d) : "f"(x), "f"(y)); return d;
}
__device__ __forceinline__ float2 unpack2(u64 v) {
    float2 r; asm("mov.b64 {%0, %1}, %2;" : "=f"(r.x), "=f"(r.y) : "l"(v)); return r;
}
__device__ __forceinline__ float wsum(float v) {
#pragma unroll
    for (int o = 16; o; o >>= 1) v += __shfl_xor_sync(0xffffffffu, v, o);
    return v;
}

#define NW 8   // warps (=batches) per block

// ---------------------------------------------------------------------------
// One warp per batch element; 8 warps/block on 64 SMs -> 2 warps per SMSP so
// stalls of one scan are issue slots of the other. The scan step is fully
// branchless: mask via selects, lazy normalizer composes (scale*=1/U,
// pend+=logU) so the once-per-chunk renorm is unconditional.
// ---------------------------------------------------------------------------
__global__ void __launch_bounds__(32 * NW, 1) crf_fused(
    const float* __restrict__ em,
    const int*   __restrict__ tags,     // int64 downgraded to int32 by harness
    const int*   __restrict__ mask,     // bool widened to int32 by harness
    const float* __restrict__ trans,
    const float* __restrict__ startT,
    const float* __restrict__ endT,
    float* __restrict__ out)
{
    __shared__ __align__(16) float4 ubuf[NW][2][32];   // [warp][buf][lane]
    __shared__ double dpart[NW];
    __shared__ unsigned is_last;

    const int warp = threadIdx.x >> 5;
    const int j    = threadIdx.x & 31;      // lane; owns states 2j, 2j+1
    const int b    = blockIdx.x * NW + warp;

    // E columns for states 2j, 2j+1 over all 64 from-states (128 regs)
    u64 Ecol2[T];
    {
        const float2* tr2 = reinterpret_cast<const float2*>(trans);
#pragma unroll
        for (int i = 0; i < T; i++) {
            float2 e = tr2[i * 32 + j];
            Ecol2[i] = pack2(__expf(e.x), __expf(e.y));
        }
    }

    const size_t bT     = (size_t)b * T;
    const size_t stride = (size_t)BB * T;
    const float2* em2base = reinterpret_cast<const float2*>(em + bT);
    const long em2stride = (long)(stride / 2);

    // ---- Phase A init (s = 0) ----
    float2 st0 = reinterpret_cast<const float2*>(startT)[j];
    float2 e0  = em2base[j];
    float u0 = __expf(st0.x + e0.x);
    float u1 = __expf(st0.y + e0.y);

    int buf = 0;
    ubuf[warp][0][j] = make_float4(u0, u0, u1, u1);
    __syncwarp();

    float U0    = wsum(u0 + u1);
    float scale = __fdividef(1.0f, U0);   // lazy, composable
    float pend  = __logf(U0);
    double C    = 0.0;

    // prefetch chunk 0 (steps 1..8)
    float2 xr[8]; int mr[8];
#pragma unroll
    for (int q = 0; q < 8; q++) {
        int s = 1 + q;
        xr[q] = em2base[(long)s * em2stride + j];
        mr[q] = mask[s * BB + b];
    }

    // one fully-branchless scan step
    auto step = [&](float2 xe, int m) {
        const ulonglong2* up = reinterpret_cast<const ulonglong2*>(ubuf[warp][buf]);
        u64 a0 = 0, a1 = 0, a2 = 0, a3 = 0;
#pragma unroll
        for (int k = 0; k < 16; k++) {
            ulonglong2 v = up[2 * k];
            ulonglong2 w = up[2 * k + 1];
            a0 = ffma2(v.x, Ecol2[4 * k],     a0);
            a1 = ffma2(v.y, Ecol2[4 * k + 1], a1);
            a2 = ffma2(w.x, Ecol2[4 * k + 2], a2);
            a3 = ffma2(w.y, Ecol2[4 * k + 3], a3);
        }
        a0 = fadd2(a0, a1);
        a2 = fadd2(a2, a3);
        a0 = fadd2(a0, a2);
        float2 tt = unpack2(a0);

        float n0 = tt.x * scale * xe.x;
        float n1 = tt.y * scale * xe.y;
        // selects (branchless): masked-out step leaves state untouched
        u0    = m ? n0 : u0;
        u1    = m ? n1 : u1;
        C    += m ? (double)pend : 0.0;
        pend  = m ? 0.0f : pend;
        scale = m ? 1.0f : scale;

        buf ^= 1;
        ubuf[warp][buf][j] = make_float4(u0, u0, u1, u1);
        __syncwarp();
    };

    for (int c = 0; c < 64; c++) {
        float2 xe[8]; int mm[8];
#pragma unroll
        for (int q = 0; q < 8; q++) {
            xe[q].x = __expf(xr[q].x);
            xe[q].y = __expf(xr[q].y);
            mm[q] = mr[q];
        }
        // prefetch next chunk (clamped; harmless re-read on last chunk)
#pragma unroll
        for (int q = 0; q < 8; q++) {
            int s = 9 + 8 * c + q;
            s = (s < S) ? s : (S - 1);
            xr[q] = em2base[(long)s * em2stride + j];
            mr[q] = mask[s * BB + b];
        }
        if (c < 63) {
#pragma unroll
            for (int q = 0; q < 8; q++) step(xe[q], mm[q]);
        } else {
#pragma unroll
            for (int q = 0; q < 7; q++) step(xe[q], mm[q]);   // steps 505..511
        }
        // unconditional composable renorm, once per chunk
        float U = wsum(u0 + u1);
        float r = __fdividef(1.0f, U);
        scale *= r;
        pend  += __logf(U);
    }

    // den = C + pend' where alpha = C + pend + log(scale*u); evaluate via
    // V = sum(scale*u*exp(end)):  den = C + pend + log(V)
    {
        float2 en = reinterpret_cast<const float2*>(endT)[j];
        float v = scale * (u0 * __expf(en.x) + u1 * __expf(en.y));
        float V = wsum(v);
        if (j == 0) g_den[b] = (float)(C + (double)pend + (double)__logf(V));
    }

    // ---- Phase B: numerator (lane j owns steps 16j..16j+15) ----
    {
        int tg[17]; int mk[16];
#pragma unroll
        for (int q = 0; q < 17; q++) {
            int s = 16 * j + q - 1;
            tg[q] = (s >= 0) ? (tags[s * BB + b] & (T - 1)) : 0;
        }
#pragma unroll
        for (int q = 0; q < 16; q++) mk[q] = mask[(16 * j + q) * BB + b];

        float acc = 0.0f;
        int cnt = 0;
#pragma unroll
        for (int q = 0; q < 16; q++) {
            int s = 16 * j + q;
            int t = tg[q + 1];
            cnt += (mk[q] ? 1 : 0);
            float e = em[stride * s + bT + t];
            if (s == 0)       acc += startT[t] + e;
            else if (mk[q])   acc += trans[tg[q] * T + t] + e;
        }
        acc = wsum(acc);
#pragma unroll
        for (int o = 16; o; o >>= 1) cnt += __shfl_xor_sync(0xffffffffu, cnt, o);
        if (j == 0) {
            int last = (cnt >= 1) ? (cnt - 1) : 0;
            int lt = tags[last * BB + b] & (T - 1);
            g_num[b] = acc + endT[lt];
        }
    }

    // ---- Phase C: ticket-elected last block computes the mean ----
    __threadfence();
    __syncthreads();
    if (threadIdx.x == 0) {
        unsigned old;
        asm volatile("atom.global.inc.u32 %0, [%1], %2;"
                     : "=r"(old) : "l"(&g_tick), "r"((unsigned)(gridDim.x - 1))
                     : "memory");
        is_last = (old == gridDim.x - 1) ? 1u : 0u;
    }
    __syncthreads();
    if (is_last) {
        int t = threadIdx.x;                 // 256 threads, 2 entries each
        double v = 0.0;
#pragma unroll
        for (int k = 0; k < 2; k++) {
            int idx = t * 2 + k;
            v += (double)g_num[idx] - (double)g_den[idx];
        }
#pragma unroll
        for (int o = 16; o; o >>= 1) v += __shfl_xor_sync(0xffffffffu, v, o);
        if (j == 0) dpart[warp] = v;
        __syncthreads();
        if (t == 0) {
            double tot = 0.0;
#pragma unroll
            for (int k = 0; k < NW; k++) tot += dpart[k];
            out[0] = (float)(tot * (1.0 / (double)BB));
        }
    }
}

// ---------------------------------------------------------------------------
extern "C" void kernel_launch(void* const* d_in, const int* in_sizes, int n_in,
                              void* d_out, int out_size)
{
    const float* em     = (const float*)d_in[0];
    const int*   tags   = (const int*)d_in[1];
    const int*   mask   = (const int*)d_in[2];
    const float* startT = (const float*)d_in[3];
    const float* endT   = (const float*)d_in[4];
    const float* trans  = (const float*)d_in[5];

    crf_fused<<<BB / NW, 32 * NW>>>(em, tags, mask, trans, startT, endT, (float*)d_out);
}

// round 10
// speedup vs baseline: 1.5837x; 1.5837x over previous
#include <cuda_runtime.h>
#include <cuda_bf16.h>

#define S 512
#define BB 512
#define T 64

__device__ float g_den[BB];
__device__ float g_num[BB];
__device__ unsigned g_tick = 0;   // wraps via atomicInc; never reset

typedef unsigned long long u64;

__device__ __forceinline__ u64 ffma2(u64 a, u64 b, u64 c) {
    u64 d; asm("fma.rn.f32x2 %0, %1, %2, %3;" : "=l"(d) : "l"(a), "l"(b), "l"(c)); return d;
}
__device__ __forceinline__ u64 fadd2(u64 a, u64 b) {
    u64 d; asm("add.rn.f32x2 %0, %1, %2;" : "=l"(d) : "l"(a), "l"(b)); return d;
}
__device__ __forceinline__ u64 pack2(float x, float y) {
    u64 d; asm("mov.b64 %0, {%1, %2};" : "=l"(d) : "f"(x), "f"(y)); return d;
}
__device__ __forceinline__ float2 unpack2(u64 v) {
    float2 r; asm("mov.b64 {%0, %1}, %2;" : "=f"(r.x), "=f"(r.y) : "l"(v)); return r;
}
__device__ __forceinline__ float wsum(float v) {
#pragma unroll
    for (int o = 16; o; o >>= 1) v += __shfl_xor_sync(0xffffffffu, v, o);
    return v;
}

// ---------------------------------------------------------------------------
// One warp per batch; lane j owns output states 2j, 2j+1.
// u published UNduplicated (float2/lane, 256B): the loaded pair {u_2i,u_2i+1}
// is consumed directly by fma.rn.f32x2 against {E[2i][out], E[2i+1][out]},
// horizontal-add at the end. 16 LDS.128 per step, loaded in two 8-load waves
// through a 32-reg window so ptxas can hoist each wave over the other's FMAs.
// grid=128 x block=128: 512 warps, 1 per SMSP on 128 SMs.
// ---------------------------------------------------------------------------
__global__ void __launch_bounds__(128, 1) crf_fused(
    const float* __restrict__ em,
    const int*   __restrict__ tags,     // int64 downgraded to int32 by harness
    const int*   __restrict__ mask,     // bool widened to int32 by harness
    const float* __restrict__ trans,
    const float* __restrict__ startT,
    const float* __restrict__ endT,
    float* __restrict__ out)
{
    __shared__ __align__(16) float2 ubuf[4][2][32];   // [warp][buf][lane]
    __shared__ double dpart[4];
    __shared__ unsigned is_last;

    const int warp = threadIdx.x >> 5;
    const int j    = threadIdx.x & 31;      // lane; owns states 2j, 2j+1
    const int b    = blockIdx.x * 4 + warp;

    // EA[p] = {E[2p][2j],   E[2p+1][2j]}
    // EB[p] = {E[2p][2j+1], E[2p+1][2j+1]}   (p = from-state pair index)
    u64 EA[T / 2], EB[T / 2];
    {
        const float2* tr2 = reinterpret_cast<const float2*>(trans);
#pragma unroll
        for (int p = 0; p < T / 2; p++) {
            float2 r0 = tr2[(2 * p) * 32 + j];       // {E[2p][2j],   E[2p][2j+1]}
            float2 r1 = tr2[(2 * p + 1) * 32 + j];   // {E[2p+1][2j], E[2p+1][2j+1]}
            EA[p] = pack2(__expf(r0.x), __expf(r1.x));
            EB[p] = pack2(__expf(r0.y), __expf(r1.y));
        }
    }

    const size_t bT     = (size_t)b * T;
    const size_t stride = (size_t)BB * T;
    const float2* em2base = reinterpret_cast<const float2*>(em + bT);
    const long em2stride = (long)(stride / 2);

    // ---- Phase A init (s = 0) ----
    float2 st0 = reinterpret_cast<const float2*>(startT)[j];
    float2 e0  = em2base[j];
    float u0 = __expf(st0.x + e0.x);
    float u1 = __expf(st0.y + e0.y);

    int buf = 0;
    ubuf[warp][0][j] = make_float2(u0, u1);
    __syncwarp();

    float U0    = wsum(u0 + u1);
    float scale = __fdividef(1.0f, U0);   // lazy, composable
    float pend  = __logf(U0);
    double C    = 0.0;

    // prefetch chunk 0 (steps 1..8)
    float2 xr[8]; int mr[8];
#pragma unroll
    for (int q = 0; q < 8; q++) {
        int s = 1 + q;
        xr[q] = em2base[(long)s * em2stride + j];
        mr[q] = mask[s * BB + b];
    }

    // one scan step (branchless; mask via selects)
    auto step = [&](float2 xe, int m) {
        const ulonglong2* up = reinterpret_cast<const ulonglong2*>(ubuf[warp][buf]);
        u64 P[16];                       // 32-reg load window (one wave)
        u64 aA0 = 0, aA1 = 0, aB0 = 0, aB1 = 0;

        // wave 1: pairs 0..15
#pragma unroll
        for (int k = 0; k < 8; k++) {
            ulonglong2 v = up[k];
            P[2 * k] = v.x; P[2 * k + 1] = v.y;
        }
#pragma unroll
        for (int p = 0; p < 16; p += 2) {
            aA0 = ffma2(P[p],     EA[p],     aA0);
            aB0 = ffma2(P[p],     EB[p],     aB0);
            aA1 = ffma2(P[p + 1], EA[p + 1], aA1);
            aB1 = ffma2(P[p + 1], EB[p + 1], aB1);
        }
        // wave 2: pairs 16..31
#pragma unroll
        for (int k = 8; k < 16; k++) {
            ulonglong2 v = up[k];
            P[2 * (k - 8)] = v.x; P[2 * (k - 8) + 1] = v.y;
        }
#pragma unroll
        for (int p = 0; p < 16; p += 2) {
            aA0 = ffma2(P[p],     EA[16 + p],     aA0);
            aB0 = ffma2(P[p],     EB[16 + p],     aB0);
            aA1 = ffma2(P[p + 1], EA[16 + p + 1], aA1);
            aB1 = ffma2(P[p + 1], EB[16 + p + 1], aB1);
        }

        float2 ta = unpack2(fadd2(aA0, aA1));
        float2 tb = unpack2(fadd2(aB0, aB1));
        float n0 = (ta.x + ta.y) * scale * xe.x;
        float n1 = (tb.x + tb.y) * scale * xe.y;

        u0    = m ? n0 : u0;
        u1    = m ? n1 : u1;
        C    += m ? (double)pend : 0.0;
        pend  = m ? 0.0f : pend;
        scale = m ? 1.0f : scale;

        buf ^= 1;
        ubuf[warp][buf][j] = make_float2(u0, u1);
        __syncwarp();
    };

    for (int c = 0; c < 64; c++) {
        float2 xe[8]; int mm[8];
#pragma unroll
        for (int q = 0; q < 8; q++) {
            xe[q].x = __expf(xr[q].x);
            xe[q].y = __expf(xr[q].y);
            mm[q] = mr[q];
        }
        // prefetch next chunk (clamped; harmless re-read on last chunk)
#pragma unroll
        for (int q = 0; q < 8; q++) {
            int s = 9 + 8 * c + q;
            s = (s < S) ? s : (S - 1);
            xr[q] = em2base[(long)s * em2stride + j];
            mr[q] = mask[s * BB + b];
        }
        if (c < 63) {
#pragma unroll
            for (int q = 0; q < 8; q++) step(xe[q], mm[q]);
        } else {
#pragma unroll
            for (int q = 0; q < 7; q++) step(xe[q], mm[q]);   // steps 505..511
        }
        // unconditional composable renorm, once per chunk
        float U = wsum(u0 + u1);
        float r = __fdividef(1.0f, U);
        scale *= r;
        pend  += __logf(U);
    }

    // den = C + pend + log( sum(scale * u * exp(end)) )
    {
        float2 en = reinterpret_cast<const float2*>(endT)[j];
        float v = scale * (u0 * __expf(en.x) + u1 * __expf(en.y));
        float V = wsum(v);
        if (j == 0) g_den[b] = (float)(C + (double)pend + (double)__logf(V));
    }

    // ---- Phase B: numerator (lane j owns steps 16j..16j+15) ----
    {
        int tg[17]; int mk[16];
#pragma unroll
        for (int q = 0; q < 17; q++) {
            int s = 16 * j + q - 1;
            tg[q] = (s >= 0) ? (tags[s * BB + b] & (T - 1)) : 0;
        }
#pragma unroll
        for (int q = 0; q < 16; q++) mk[q] = mask[(16 * j + q) * BB + b];

        float acc = 0.0f;
        int cnt = 0;
#pragma unroll
        for (int q = 0; q < 16; q++) {
            int s = 16 * j + q;
            int t = tg[q + 1];
            cnt += (mk[q] ? 1 : 0);
            float e = em[stride * s + bT + t];
            if (s == 0)       acc += startT[t] + e;
            else if (mk[q])   acc += trans[tg[q] * T + t] + e;
        }
        acc = wsum(acc);
#pragma unroll
        for (int o = 16; o; o >>= 1) cnt += __shfl_xor_sync(0xffffffffu, cnt, o);
        if (j == 0) {
            int last = (cnt >= 1) ? (cnt - 1) : 0;
            int lt = tags[last * BB + b] & (T - 1);
            g_num[b] = acc + endT[lt];
        }
    }

    // ---- Phase C: ticket-elected last block computes the mean ----
    __threadfence();
    __syncthreads();
    if (threadIdx.x == 0) {
        unsigned old;
        asm volatile("atom.global.inc.u32 %0, [%1], %2;"
                     : "=r"(old) : "l"(&g_tick), "r"((unsigned)(gridDim.x - 1))
                     : "memory");
        is_last = (old == gridDim.x - 1) ? 1u : 0u;
    }
    __syncthreads();
    if (is_last) {
        int t = threadIdx.x;                 // 128 threads, 4 entries each
        double v = 0.0;
#pragma unroll
        for (int k = 0; k < 4; k++) {
            int idx = t * 4 + k;
            v += (double)g_num[idx] - (double)g_den[idx];
        }
#pragma unroll
        for (int o = 16; o; o >>= 1) v += __shfl_xor_sync(0xffffffffu, v, o);
        if (j == 0) dpart[warp] = v;
        __syncthreads();
        if (t == 0) {
            double tot = dpart[0] + dpart[1] + dpart[2] + dpart[3];
            out[0] = (float)(tot * (1.0 / (double)BB));
        }
    }
}

// ---------------------------------------------------------------------------
extern "C" void kernel_launch(void* const* d_in, const int* in_sizes, int n_in,
                              void* d_out, int out_size)
{
    const float* em     = (const float*)d_in[0];
    const int*   tags   = (const int*)d_in[1];
    const int*   mask   = (const int*)d_in[2];
    const float* startT = (const float*)d_in[3];
    const float* endT   = (const float*)d_in[4];
    const float* trans  = (const float*)d_in[5];

    crf_fused<<<BB / 4, 128>>>(em, tags, mask, trans, startT, endT, (float*)d_out);
}

// round 11
// speedup vs baseline: 1.7537x; 1.1073x over previous
#include <cuda_runtime.h>
#include <cuda_bf16.h>

#define S 512
#define BB 512
#define T 64

__device__ float g_den[BB];
__device__ float g_num[BB];
__device__ unsigned g_tick = 0;   // wraps via atomicInc; never reset

typedef unsigned long long u64;

__device__ __forceinline__ u64 ffma2(u64 a, u64 b, u64 c) {
    u64 d; asm("fma.rn.f32x2 %0, %1, %2, %3;" : "=l"(d) : "l"(a), "l"(b), "l"(c)); return d;
}
__device__ __forceinline__ u64 fadd2(u64 a, u64 b) {
    u64 d; asm("add.rn.f32x2 %0, %1, %2;" : "=l"(d) : "l"(a), "l"(b)); return d;
}
__device__ __forceinline__ u64 pack2(float x, float y) {
    u64 d; asm("mov.b64 %0, {%1, %2};" : "=l"(d) : "f"(x), "f"(y)); return d;
}
__device__ __forceinline__ float2 unpack2(u64 v) {
    float2 r; asm("mov.b64 {%0, %1}, %2;" : "=f"(r.x), "=f"(r.y) : "l"(v)); return r;
}
__device__ __forceinline__ float wsum(float v) {
#pragma unroll
    for (int o = 16; o; o >>= 1) v += __shfl_xor_sync(0xffffffffu, v, o);
    return v;
}
#define PAIR_BAR(id) asm volatile("bar.sync %0, 64;" :: "r"(id) : "memory")

// ---------------------------------------------------------------------------
// Two warps per batch element (a "pair"); each warp owns 32 output states
// (one per lane, o = half*32 + j). Per step per lane: 16 LDS.128 + 32 FFMA2,
// pair-synced with a named barrier (64 threads). Two batches per 128-thread
// block; ~2 blocks/SM -> 2 warps per SMSP so one scan's stalls are the
// other's issue slots. Lazy composable renorm once per 8-step chunk.
// ---------------------------------------------------------------------------
__global__ void __launch_bounds__(128, 2) crf_fused(
    const float* __restrict__ em,
    const int*   __restrict__ tags,     // int64 downgraded to int32 by harness
    const int*   __restrict__ mask,     // bool widened to int32 by harness
    const float* __restrict__ trans,
    const float* __restrict__ startT,
    const float* __restrict__ endT,
    float* __restrict__ out)
{
    __shared__ __align__(16) float ubuf[2][2][T];   // [pair][buf][state]
    __shared__ float spart[2][2];                   // [pair][half]
    __shared__ double dpart[4];
    __shared__ unsigned is_last;

    const int warp = threadIdx.x >> 5;   // 0..3
    const int pair = warp >> 1;          // batch slot in block
    const int half = warp & 1;           // 0: states 0..31, 1: states 32..63
    const int j    = threadIdx.x & 31;
    const int o    = half * 32 + j;      // owned output state
    const int bid  = pair + 1;           // named barrier id (1 or 2)
    const int b    = blockIdx.x * 2 + pair;

    // E column for state o over from-state pairs: Ecol2[p]={E[2p][o],E[2p+1][o]}
    u64 Ecol2[T / 2];
#pragma unroll
    for (int p = 0; p < T / 2; p++) {
        Ecol2[p] = pack2(__expf(trans[(2 * p) * T + o]),
                         __expf(trans[(2 * p + 1) * T + o]));
    }

    const size_t bT     = (size_t)b * T;
    const size_t stride = (size_t)BB * T;

    // ---- Phase A init (s = 0) ----
    float u = __expf(startT[o] + em[bT + o]);
    int buf = 0;
    ubuf[pair][0][o] = u;
    float pw = wsum(u);
    if (j == 0) spart[pair][half] = pw;
    PAIR_BAR(bid);

    float U0    = spart[pair][0] + spart[pair][1];
    float scale = __fdividef(1.0f, U0);   // lazy, composable
    float pend  = __logf(U0);
    float C     = 0.0f;                    // |den|~2400, float abs err ~1e-3 ok

    // prefetch chunk 0 (steps 1..8)
    float xr[8]; int mr[8];
#pragma unroll
    for (int q = 0; q < 8; q++) {
        int s = 1 + q;
        xr[q] = em[stride * s + bT + o];
        mr[q] = mask[s * BB + b];
    }

    // one scan step (branchless), with optional chunk-end partial publish
    auto step = [&](float xe, int m, bool dn) {
        const ulonglong2* up = reinterpret_cast<const ulonglong2*>(ubuf[pair][buf]);
        u64 a0 = 0, a1 = 0;
#pragma unroll
        for (int k = 0; k < 16; k++) {
            ulonglong2 v = up[k];
            a0 = ffma2(v.x, Ecol2[2 * k],     a0);
            a1 = ffma2(v.y, Ecol2[2 * k + 1], a1);
        }
        float2 tt = unpack2(fadd2(a0, a1));
        float n = (tt.x + tt.y) * scale * xe;

        u     = m ? n : u;
        C    += m ? pend : 0.0f;
        pend  = m ? 0.0f : pend;
        scale = m ? 1.0f : scale;

        buf ^= 1;
        ubuf[pair][buf][o] = u;
        if (dn) {                          // publish warp partial before bar
            float w = wsum(u);
            if (j == 0) spart[pair][half] = w;
        }
        PAIR_BAR(bid);
        if (dn) {                          // composable renorm
            float U = spart[pair][0] + spart[pair][1];
            scale *= __fdividef(1.0f, U);
            pend  += __logf(U);
        }
    };

    for (int c = 0; c < 64; c++) {
        float xe[8]; int mm[8];
#pragma unroll
        for (int q = 0; q < 8; q++) { xe[q] = __expf(xr[q]); mm[q] = mr[q]; }
        // prefetch next chunk (clamped; harmless re-read on last chunk)
#pragma unroll
        for (int q = 0; q < 8; q++) {
            int s = 9 + 8 * c + q;
            s = (s < S) ? s : (S - 1);
            xr[q] = em[stride * s + bT + o];
            mr[q] = mask[s * BB + b];
        }
        if (c < 63) {
#pragma unroll
            for (int q = 0; q < 8; q++) step(xe[q], mm[q], q == 7);
        } else {
#pragma unroll
            for (int q = 0; q < 7; q++) step(xe[q], mm[q], q == 6);
        }
    }

    // den = C + pend + log( sum(scale * u * exp(end)) )
    {
        float v = scale * u * __expf(endT[o]);
        float w = wsum(v);
        if (j == 0) spart[pair][half] = w;
        PAIR_BAR(bid);
        if (o == 0) {
            float V = spart[pair][0] + spart[pair][1];
            g_den[b] = C + pend + __logf(V);
        }
    }

    // ---- Phase B: numerator (warp 'half==0' of each pair; lane j owns
    //      steps 16j..16j+15) ----
    if (half == 0) {
        int tg[17]; int mk[16];
#pragma unroll
        for (int q = 0; q < 17; q++) {
            int s = 16 * j + q - 1;
            tg[q] = (s >= 0) ? (tags[s * BB + b] & (T - 1)) : 0;
        }
#pragma unroll
        for (int q = 0; q < 16; q++) mk[q] = mask[(16 * j + q) * BB + b];

        float acc = 0.0f;
        int cnt = 0;
#pragma unroll
        for (int q = 0; q < 16; q++) {
            int s = 16 * j + q;
            int t = tg[q + 1];
            cnt += (mk[q] ? 1 : 0);
            float e = em[stride * s + bT + t];
            if (s == 0)       acc += startT[t] + e;
            else if (mk[q])   acc += trans[tg[q] * T + t] + e;
        }
        acc = wsum(acc);
#pragma unroll
        for (int ofs = 16; ofs; ofs >>= 1) cnt += __shfl_xor_sync(0xffffffffu, cnt, ofs);
        if (j == 0) {
            int last = (cnt >= 1) ? (cnt - 1) : 0;
            int lt = tags[last * BB + b] & (T - 1);
            g_num[b] = acc + endT[lt];
        }
    }

    // ---- Phase C: ticket-elected last block computes the mean ----
    __threadfence();
    __syncthreads();
    if (threadIdx.x == 0) {
        unsigned old;
        asm volatile("atom.global.inc.u32 %0, [%1], %2;"
                     : "=r"(old) : "l"(&g_tick), "r"((unsigned)(gridDim.x - 1))
                     : "memory");
        is_last = (old == gridDim.x - 1) ? 1u : 0u;
    }
    __syncthreads();
    if (is_last) {
        int t = threadIdx.x;                 // 128 threads, 4 entries each
        double v = 0.0;
#pragma unroll
        for (int k = 0; k < 4; k++) {
            int idx = t * 4 + k;
            v += (double)g_num[idx] - (double)g_den[idx];
        }
#pragma unroll
        for (int ofs = 16; ofs; ofs >>= 1) v += __shfl_xor_sync(0xffffffffu, v, ofs);
        if (j == 0) dpart[warp] = v;
        __syncthreads();
        if (t == 0) {
            double tot = dpart[0] + dpart[1] + dpart[2] + dpart[3];
            out[0] = (float)(tot * (1.0 / (double)BB));
        }
    }
}

// ---------------------------------------------------------------------------
extern "C" void kernel_launch(void* const* d_in, const int* in_sizes, int n_in,
                              void* d_out, int out_size)
{
    const float* em     = (const float*)d_in[0];
    const int*   tags   = (const int*)d_in[1];
    const int*   mask   = (const int*)d_in[2];
    const float* startT = (const float*)d_in[3];
    const float* endT   = (const float*)d_in[4];
    const float* trans  = (const float*)d_in[5];

    crf_fused<<<BB / 2, 128>>>(em, tags, mask, trans, startT, endT, (float*)d_out);
}

// round 12
// speedup vs baseline: 1.8466x; 1.0530x over previous
#include <cuda_runtime.h>
#include <cuda_bf16.h>

#define S 512
#define BB 512
#define T 64

__device__ float g_den[BB];
__device__ float g_num[BB];
__device__ unsigned g_tick = 0;   // wraps via atomicInc; never reset

typedef unsigned long long u64;

__device__ __forceinline__ u64 ffma2(u64 a, u64 b, u64 c) {
    u64 d; asm("fma.rn.f32x2 %0, %1, %2, %3;" : "=l"(d) : "l"(a), "l"(b), "l"(c)); return d;
}
__device__ __forceinline__ u64 fadd2(u64 a, u64 b) {
    u64 d; asm("add.rn.f32x2 %0, %1, %2;" : "=l"(d) : "l"(a), "l"(b)); return d;
}
__device__ __forceinline__ u64 pack2(float x, float y) {
    u64 d; asm("mov.b64 %0, {%1, %2};" : "=l"(d) : "f"(x), "f"(y)); return d;
}
__device__ __forceinline__ float2 unpack2(u64 v) {
    float2 r; asm("mov.b64 {%0, %1}, %2;" : "=f"(r.x), "=f"(r.y) : "l"(v)); return r;
}
__device__ __forceinline__ float wsum(float v) {
#pragma unroll
    for (int o = 16; o; o >>= 1) v += __shfl_xor_sync(0xffffffffu, v, o);
    return v;
}
#define PAIR_BAR(id) asm volatile("bar.sync %0, 64;" :: "r"(id) : "memory")

// ---------------------------------------------------------------------------
// Two warps per batch (pair); each warp owns 32 output states (lane owns one).
// Invariant: alpha_j = K + log(u_j) with scalar K — so the scan step is just
// u' = matvec(u) * xe (plus one mask select). Scale/pend bookkeeping touches
// only the chunk-start step. Renormalizer uses step-7's u so its shfl chain
// overlaps step-8's matvec issue instead of extending the critical path.
// ---------------------------------------------------------------------------
__global__ void __launch_bounds__(128, 2) crf_fused(
    const float* __restrict__ em,
    const int*   __restrict__ tags,     // int64 downgraded to int32 by harness
    const int*   __restrict__ mask,     // bool widened to int32 by harness
    const float* __restrict__ trans,
    const float* __restrict__ startT,
    const float* __restrict__ endT,
    float* __restrict__ out)
{
    __shared__ __align__(16) float ubuf[2][2][T];   // [pair][buf][state]
    __shared__ float spart[2][2];                   // [pair][half]
    __shared__ double dpart[4];
    __shared__ unsigned is_last;

    const int warp = threadIdx.x >> 5;   // 0..3
    const int pair = warp >> 1;
    const int half = warp & 1;
    const int j    = threadIdx.x & 31;
    const int o    = half * 32 + j;      // owned output state
    const int bid  = pair + 1;           // named barrier id
    const int b    = blockIdx.x * 2 + pair;

    // E column for state o over from-state pairs
    u64 Ecol2[T / 2];
#pragma unroll
    for (int p = 0; p < T / 2; p++) {
        Ecol2[p] = pack2(__expf(trans[(2 * p) * T + o]),
                         __expf(trans[(2 * p + 1) * T + o]));
    }

    const size_t bT     = (size_t)b * T;
    const size_t stride = (size_t)BB * T;

    // ---- init (s = 0) ----
    float u = __expf(startT[o] + em[bT + o]);
    int buf = 0;
    ubuf[pair][0][o] = u;
    float pw = wsum(u);
    if (j == 0) spart[pair][half] = pw;
    PAIR_BAR(bid);

    float U0    = spart[pair][0] + spart[pair][1];
    float scale = __fdividef(1.0f, U0);   // pending, applied at chunk start
    float pend  = __logf(U0);
    float K     = 0.0f;

    // prefetch chunk 0 (steps 1..8)
    float xr[8]; int mr[8];
#pragma unroll
    for (int q = 0; q < 8; q++) {
        int s = 1 + q;
        xr[q] = em[stride * s + bT + o];
        mr[q] = mask[s * BB + b];
    }

    // 4-accumulator matvec over the current buffer
    auto matvec = [&]() -> float {
        const ulonglong2* up = reinterpret_cast<const ulonglong2*>(ubuf[pair][buf]);
        u64 a0 = 0, a1 = 0, a2 = 0, a3 = 0;
#pragma unroll
        for (int k = 0; k < 8; k++) {
            ulonglong2 v = up[2 * k];
            ulonglong2 w = up[2 * k + 1];
            a0 = ffma2(v.x, Ecol2[4 * k],     a0);
            a1 = ffma2(v.y, Ecol2[4 * k + 1], a1);
            a2 = ffma2(w.x, Ecol2[4 * k + 2], a2);
            a3 = ffma2(w.y, Ecol2[4 * k + 3], a3);
        }
        float2 tt = unpack2(fadd2(fadd2(a0, a1), fadd2(a2, a3)));
        return tt.x + tt.y;
    };

    for (int c = 0; c < 64; c++) {
        float xe[8]; int mm[8];
#pragma unroll
        for (int q = 0; q < 8; q++) { xe[q] = __expf(xr[q]); mm[q] = mr[q]; }
        // prefetch next chunk (clamped)
#pragma unroll
        for (int q = 0; q < 8; q++) {
            int s = 9 + 8 * c + q;
            s = (s < S) ? s : (S - 1);
            xr[q] = em[stride * s + bT + o];
            mr[q] = mask[s * BB + b];
        }

        const int nq = (c < 63) ? 8 : 7;
#pragma unroll
        for (int q = 0; q < 8; q++) {
            if (q >= nq) break;
            float t = matvec();
            float n;
            if (q == 0) {                      // chunk start: apply pending renorm
                n = t * (xe[0] * scale);
                int m = mm[0];
                u     = m ? n : u;
                K    += m ? pend : 0.0f;
                pend  = m ? 0.0f : pend;
                scale = m ? 1.0f : scale;
            } else {
                n = t * xe[q];
                u = mm[q] ? n : u;
            }
            buf ^= 1;
            ubuf[pair][buf][o] = u;
            if (q == 6 && c < 63) {            // publish U from step-7's u;
                float w = wsum(u);             // chain overlaps step-8 issue
                if (j == 0) spart[pair][half] = w;
            }
            PAIR_BAR(bid);
        }
        if (c < 63) {                          // consume after step-8's bar
            float U = spart[pair][0] + spart[pair][1];
            scale *= __fdividef(1.0f, U);
            pend  += __logf(U);
        }
    }

    // den = K + pend + log( sum(scale * u * exp(end)) )
    {
        float v = scale * u * __expf(endT[o]);
        float w = wsum(v);
        if (j == 0) spart[pair][half] = w;
        PAIR_BAR(bid);
        if (o == 0) {
            float V = spart[pair][0] + spart[pair][1];
            g_den[b] = K + pend + __logf(V);
        }
    }

    // ---- numerator (warp half==0 of each pair; lane j owns steps 16j..16j+15)
    if (half == 0) {
        int tg[17]; int mk[16];
#pragma unroll
        for (int q = 0; q < 17; q++) {
            int s = 16 * j + q - 1;
            tg[q] = (s >= 0) ? (tags[s * BB + b] & (T - 1)) : 0;
        }
#pragma unroll
        for (int q = 0; q < 16; q++) mk[q] = mask[(16 * j + q) * BB + b];

        float acc = 0.0f;
        int cnt = 0;
#pragma unroll
        for (int q = 0; q < 16; q++) {
            int s = 16 * j + q;
            int t = tg[q + 1];
            cnt += (mk[q] ? 1 : 0);
            float e = em[stride * s + bT + t];
            if (s == 0)       acc += startT[t] + e;
            else if (mk[q])   acc += trans[tg[q] * T + t] + e;
        }
        acc = wsum(acc);
#pragma unroll
        for (int ofs = 16; ofs; ofs >>= 1) cnt += __shfl_xor_sync(0xffffffffu, cnt, ofs);
        if (j == 0) {
            int last = (cnt >= 1) ? (cnt - 1) : 0;
            int lt = tags[last * BB + b] & (T - 1);
            g_num[b] = acc + endT[lt];
        }
    }

    // ---- ticket-elected last block computes the mean ----
    __threadfence();
    __syncthreads();
    if (threadIdx.x == 0) {
        unsigned old;
        asm volatile("atom.global.inc.u32 %0, [%1], %2;"
                     : "=r"(old) : "l"(&g_tick), "r"((unsigned)(gridDim.x - 1))
                     : "memory");
        is_last = (old == gridDim.x - 1) ? 1u : 0u;
    }
    __syncthreads();
    if (is_last) {
        int t = threadIdx.x;
        double v = 0.0;
#pragma unroll
        for (int k = 0; k < 4; k++) {
            int idx = t * 4 + k;
            v += (double)g_num[idx] - (double)g_den[idx];
        }
#pragma unroll
        for (int ofs = 16; ofs; ofs >>= 1) v += __shfl_xor_sync(0xffffffffu, v, ofs);
        if (j == 0) dpart[warp] = v;
        __syncthreads();
        if (t == 0) {
            double tot = dpart[0] + dpart[1] + dpart[2] + dpart[3];
            out[0] = (float)(tot * (1.0 / (double)BB));
        }
    }
}

// ---------------------------------------------------------------------------
extern "C" void kernel_launch(void* const* d_in, const int* in_sizes, int n_in,
                              void* d_out, int out_size)
{
    const float* em     = (const float*)d_in[0];
    const int*   tags   = (const int*)d_in[1];
    const int*   mask   = (const int*)d_in[2];
    const float* startT = (const float*)d_in[3];
    const float* endT   = (const float*)d_in[4];
    const float* trans  = (const float*)d_in[5];

    crf_fused<<<BB / 2, 128>>>(em, tags, mask, trans, startT, endT, (float*)d_out);
}